// round 2
// baseline (speedup 1.0000x reference)
#include <cuda_runtime.h>

#define N_NODES 50000
#define N_EDGES 800000
#define D       96
#define H2      32
#define OUTD    4
#define CH      (D/4)   // 24 float4 chunks per row

// Scratch (no allocations allowed)
__device__ float g_z1[N_NODES * D];
__device__ float g_h1[N_NODES * D];
__device__ float g_z2[N_NODES * D];

// z[i] = (1+eps) * x[i], vectorized float4
__global__ void k_scale(const float* __restrict__ x, const float* __restrict__ eps,
                        float* __restrict__ z, int n4) {
    int i = blockIdx.x * blockDim.x + threadIdx.x;
    if (i < n4) {
        float s = 1.0f + *eps;
        float4 v = reinterpret_cast<const float4*>(x)[i];
        v.x *= s; v.y *= s; v.z *= s; v.w *= s;
        reinterpret_cast<float4*>(z)[i] = v;
    }
}

// Edge scatter: z[dst] += feat[src], one thread per (edge, float4 chunk),
// vectorized L2 reduction (red.global.add.v4.f32)
__global__ void k_agg(const float* __restrict__ feat, const int* __restrict__ ei,
                      float* __restrict__ z) {
    int idx = blockIdx.x * blockDim.x + threadIdx.x;
    if (idx >= N_EDGES * CH) return;
    int e = idx / CH;
    int c = idx - e * CH;
    int s = ei[e];
    int d = ei[N_EDGES + e];
    float4 v = reinterpret_cast<const float4*>(feat)[s * CH + c];
    float* p = z + ((long long)d * D + c * 4);
    asm volatile("red.global.add.v4.f32 [%0], {%1,%2,%3,%4};"
                 :: "l"(p), "f"(v.x), "f"(v.y), "f"(v.z), "f"(v.w) : "memory");
}

// MLP1: h = relu( relu(z@W1a + b1a) @ W1b + b1b )
// blockDim = 384 = 4 groups x 96 cols. 32 rows per block.
// Weights staged in smem (one at a time), intermediate t in smem.
#define ROWS1   32
#define GROUPS1 4
__global__ __launch_bounds__(GROUPS1 * D)
void k_mlp1(const float* __restrict__ z,
            const float* __restrict__ W1a, const float* __restrict__ b1a,
            const float* __restrict__ W1b, const float* __restrict__ b1b,
            float* __restrict__ h) {
    __shared__ float W_sm[D * D];        // 36864 B
    __shared__ float t_sm[ROWS1 * D];    // 12288 B  (total 48 KB)
    const int tid = threadIdx.x;
    const int g = tid / D;               // 0..3
    const int c = tid - g * D;           // 0..95
    const int row0 = blockIdx.x * ROWS1;
    const int RPG = ROWS1 / GROUPS1;     // 8

    for (int i = tid; i < D * D; i += GROUPS1 * D) W_sm[i] = W1a[i];
    __syncthreads();

    float bias = b1a[c];
    for (int rr = 0; rr < RPG; rr++) {
        int r = g * RPG + rr;
        int row = row0 + r;
        if (row < N_NODES) {
            float acc = bias;
            const float* zr = z + (long long)row * D;
            #pragma unroll 16
            for (int k = 0; k < D; k++) acc = fmaf(__ldg(zr + k), W_sm[k * D + c], acc);
            t_sm[r * D + c] = fmaxf(acc, 0.0f);
        }
    }
    __syncthreads();
    for (int i = tid; i < D * D; i += GROUPS1 * D) W_sm[i] = W1b[i];
    __syncthreads();

    bias = b1b[c];
    for (int rr = 0; rr < RPG; rr++) {
        int r = g * RPG + rr;
        int row = row0 + r;
        if (row < N_NODES) {
            float acc = bias;
            #pragma unroll 16
            for (int k = 0; k < D; k++) acc = fmaf(t_sm[r * D + k], W_sm[k * D + c], acc);
            h[(long long)row * D + c] = fmaxf(acc, 0.0f);
        }
    }
}

// MLP2 + head: h2 = relu( relu(z2@W2a + b2a) @ W2b + b2b ); out = h2@Wh + bh
// blockDim = 256 = 8 groups x 32 cols. 64 rows per block.
#define ROWS2 64
__global__ __launch_bounds__(256)
void k_mlp2(const float* __restrict__ z2,
            const float* __restrict__ W2a, const float* __restrict__ b2a,
            const float* __restrict__ W2b, const float* __restrict__ b2b,
            const float* __restrict__ Wh,  const float* __restrict__ bh,
            float* __restrict__ out) {
    __shared__ float W2a_sm[D * H2];      // 12288 B
    __shared__ float W2b_sm[H2 * H2];     // 4096 B
    __shared__ float Wh_sm[H2 * OUTD];    // 512 B
    __shared__ float a_sm[ROWS2 * H2];    // 8192 B
    __shared__ float b_sm[ROWS2 * H2];    // 8192 B
    const int tid = threadIdx.x;
    for (int i = tid; i < D * H2;    i += 256) W2a_sm[i] = W2a[i];
    for (int i = tid; i < H2 * H2;   i += 256) W2b_sm[i] = W2b[i];
    for (int i = tid; i < H2 * OUTD; i += 256) Wh_sm[i]  = Wh[i];
    __syncthreads();

    const int g = tid / H2;   // 0..7
    const int j = tid - g * H2;
    const int row0 = blockIdx.x * ROWS2;
    const int RPG = ROWS2 / 8;  // 8
    float bja = b2a[j], bjb = b2b[j];

    for (int rr = 0; rr < RPG; rr++) {
        int r = g * RPG + rr;
        int row = row0 + r;
        if (row < N_NODES) {
            float acc = bja;
            const float* zr = z2 + (long long)row * D;
            #pragma unroll 16
            for (int k = 0; k < D; k++) acc = fmaf(__ldg(zr + k), W2a_sm[k * H2 + j], acc);
            a_sm[r * H2 + j] = fmaxf(acc, 0.0f);
        }
    }
    __syncthreads();
    for (int rr = 0; rr < RPG; rr++) {
        int r = g * RPG + rr;
        int row = row0 + r;
        if (row < N_NODES) {
            float acc = bjb;
            #pragma unroll
            for (int k = 0; k < H2; k++) acc = fmaf(a_sm[r * H2 + k], W2b_sm[k * H2 + j], acc);
            b_sm[r * H2 + j] = fmaxf(acc, 0.0f);
        }
    }
    __syncthreads();
    {
        int r = tid / OUTD;           // 0..63
        int o = tid - r * OUTD;       // 0..3
        int row = row0 + r;
        if (row < N_NODES) {
            float acc = bh[o];
            #pragma unroll
            for (int k = 0; k < H2; k++) acc = fmaf(b_sm[r * H2 + k], Wh_sm[k * OUTD + o], acc);
            out[(long long)row * OUTD + o] = acc;
        }
    }
}

extern "C" void kernel_launch(void* const* d_in, const int* in_sizes, int n_in,
                              void* d_out, int out_size) {
    const float* x    = (const float*)d_in[0];
    const int*   ei   = (const int*)  d_in[1];
    const float* eps1 = (const float*)d_in[2];
    const float* eps2 = (const float*)d_in[3];
    const float* W1a  = (const float*)d_in[4];
    const float* b1a  = (const float*)d_in[5];
    const float* W1b  = (const float*)d_in[6];
    const float* b1b  = (const float*)d_in[7];
    const float* W2a  = (const float*)d_in[8];
    const float* b2a  = (const float*)d_in[9];
    const float* W2b  = (const float*)d_in[10];
    const float* b2b  = (const float*)d_in[11];
    const float* Wh   = (const float*)d_in[12];
    const float* bh   = (const float*)d_in[13];
    float* out = (float*)d_out;

    float *z1, *h1, *z2;
    cudaGetSymbolAddress((void**)&z1, g_z1);
    cudaGetSymbolAddress((void**)&h1, g_h1);
    cudaGetSymbolAddress((void**)&z2, g_z2);

    const int n4 = N_NODES * D / 4;                 // 1.2M float4
    const int scale_blocks = (n4 + 255) / 256;
    const int agg_threads = N_EDGES * CH;           // 19.2M
    const int agg_blocks = (agg_threads + 255) / 256;
    const int mlp1_blocks = (N_NODES + ROWS1 - 1) / ROWS1;
    const int mlp2_blocks = (N_NODES + ROWS2 - 1) / ROWS2;

    // Layer 1
    k_scale<<<scale_blocks, 256>>>(x, eps1, z1, n4);
    k_agg<<<agg_blocks, 256>>>(x, ei, z1);
    k_mlp1<<<mlp1_blocks, GROUPS1 * D>>>(z1, W1a, b1a, W1b, b1b, h1);

    // Layer 2
    k_scale<<<scale_blocks, 256>>>(h1, eps2, z2, n4);
    k_agg<<<agg_blocks, 256>>>(h1, ei, z2);
    k_mlp2<<<mlp2_blocks, 256>>>(z2, W2a, b2a, W2b, b2b, Wh, bh, out);
}

// round 3
// speedup vs baseline: 1.1645x; 1.1645x over previous
#include <cuda_runtime.h>

#define N_NODES 50000
#define N_EDGES 800000
#define D       96
#define H2      32
#define OUTD    4
#define CH      (D/4)        // 24 float4 chunks per row
#define SCAN_B  1024
#define SCAN_NB ((N_NODES + SCAN_B - 1) / SCAN_B)   // 49

// Scratch (no allocations allowed)
__device__ float g_z1[N_NODES * D];
__device__ float g_h1[N_NODES * D];
__device__ float g_z2[N_NODES * D];
__device__ int   g_deg[N_NODES];
__device__ int   g_rowptr[N_NODES + 1];
__device__ int   g_cursor[N_NODES];
__device__ int   g_bsum[SCAN_NB];
__device__ int   g_ebuf[N_EDGES];

// ---------------- CSR build ----------------

__global__ void k_hist(const int* __restrict__ ei, int* __restrict__ deg) {
    int e = blockIdx.x * blockDim.x + threadIdx.x;
    if (e < N_EDGES) atomicAdd(&deg[ei[N_EDGES + e]], 1);
}

// per-block exclusive scan of deg -> rowptr (partial), block sums -> bsum
__global__ __launch_bounds__(SCAN_B)
void k_scan1(const int* __restrict__ deg, int* __restrict__ rowptr, int* __restrict__ bsum) {
    __shared__ int s[SCAN_B];
    int t = threadIdx.x;
    int i = blockIdx.x * SCAN_B + t;
    int v = (i < N_NODES) ? deg[i] : 0;
    s[t] = v;
    __syncthreads();
    for (int off = 1; off < SCAN_B; off <<= 1) {
        int add = (t >= off) ? s[t - off] : 0;
        __syncthreads();
        s[t] += add;
        __syncthreads();
    }
    if (i < N_NODES) rowptr[i] = s[t] - v;   // exclusive
    if (t == SCAN_B - 1) bsum[blockIdx.x] = s[t];
}

// scan block sums (single block)
__global__ void k_scan2(int* __restrict__ bsum) {
    __shared__ int s[64];
    int t = threadIdx.x;
    int v = (t < SCAN_NB) ? bsum[t] : 0;
    s[t] = v;
    __syncthreads();
    for (int off = 1; off < 64; off <<= 1) {
        int add = (t >= off) ? s[t - off] : 0;
        __syncthreads();
        s[t] += add;
        __syncthreads();
    }
    if (t < SCAN_NB) bsum[t] = s[t] - v;     // exclusive
}

// add block offsets; also init cursor and rowptr[N]
__global__ __launch_bounds__(SCAN_B)
void k_scan3(int* __restrict__ rowptr, const int* __restrict__ bsum, int* __restrict__ cursor) {
    int i = blockIdx.x * SCAN_B + threadIdx.x;
    if (i < N_NODES) {
        int r = rowptr[i] + bsum[blockIdx.x];
        rowptr[i] = r;
        cursor[i] = r;
    }
    if (i == 0) rowptr[N_NODES] = N_EDGES;
}

__global__ void k_fill(const int* __restrict__ ei, int* __restrict__ cursor,
                       int* __restrict__ ebuf) {
    int e = blockIdx.x * blockDim.x + threadIdx.x;
    if (e < N_EDGES) {
        int dst = ei[N_EDGES + e];
        int pos = atomicAdd(&cursor[dst], 1);
        ebuf[pos] = ei[e];
    }
}

// ---------------- fused scale + gather-aggregate ----------------
// z[i] = (1+eps)*feat[i] + sum_{j in N(i)} feat[j]
// one warp per node; lanes 0..23 each own one float4 chunk
__global__ __launch_bounds__(256)
void k_gagg(const float* __restrict__ feat, const float* __restrict__ eps,
            const int* __restrict__ rowptr, const int* __restrict__ ebuf,
            float* __restrict__ z) {
    int warp = (blockIdx.x * blockDim.x + threadIdx.x) >> 5;
    int lane = threadIdx.x & 31;
    if (warp >= N_NODES) return;
    int beg = rowptr[warp];
    int end = rowptr[warp + 1];
    const float4* f4 = reinterpret_cast<const float4*>(feat);
    float4 acc = make_float4(0.f, 0.f, 0.f, 0.f);
    if (lane < CH) {
        float s = 1.0f + *eps;
        float4 v = f4[warp * CH + lane];
        acc.x = s * v.x; acc.y = s * v.y; acc.z = s * v.z; acc.w = s * v.w;
    }
    for (int e = beg; e < end; e++) {
        int src = __ldg(&ebuf[e]);           // uniform across warp -> broadcast
        if (lane < CH) {
            float4 v = f4[src * CH + lane];
            acc.x += v.x; acc.y += v.y; acc.z += v.z; acc.w += v.w;
        }
    }
    if (lane < CH) reinterpret_cast<float4*>(z)[warp * CH + lane] = acc;
}

// ---------------- MLPs (unchanged from R1) ----------------
#define ROWS1   32
#define GROUPS1 4
__global__ __launch_bounds__(GROUPS1 * D)
void k_mlp1(const float* __restrict__ z,
            const float* __restrict__ W1a, const float* __restrict__ b1a,
            const float* __restrict__ W1b, const float* __restrict__ b1b,
            float* __restrict__ h) {
    __shared__ float W_sm[D * D];
    __shared__ float t_sm[ROWS1 * D];
    const int tid = threadIdx.x;
    const int g = tid / D;
    const int c = tid - g * D;
    const int row0 = blockIdx.x * ROWS1;
    const int RPG = ROWS1 / GROUPS1;

    for (int i = tid; i < D * D; i += GROUPS1 * D) W_sm[i] = W1a[i];
    __syncthreads();

    float bias = b1a[c];
    for (int rr = 0; rr < RPG; rr++) {
        int r = g * RPG + rr;
        int row = row0 + r;
        if (row < N_NODES) {
            float acc = bias;
            const float* zr = z + (long long)row * D;
            #pragma unroll 16
            for (int k = 0; k < D; k++) acc = fmaf(__ldg(zr + k), W_sm[k * D + c], acc);
            t_sm[r * D + c] = fmaxf(acc, 0.0f);
        }
    }
    __syncthreads();
    for (int i = tid; i < D * D; i += GROUPS1 * D) W_sm[i] = W1b[i];
    __syncthreads();

    bias = b1b[c];
    for (int rr = 0; rr < RPG; rr++) {
        int r = g * RPG + rr;
        int row = row0 + r;
        if (row < N_NODES) {
            float acc = bias;
            #pragma unroll 16
            for (int k = 0; k < D; k++) acc = fmaf(t_sm[r * D + k], W_sm[k * D + c], acc);
            h[(long long)row * D + c] = fmaxf(acc, 0.0f);
        }
    }
}

#define ROWS2 64
__global__ __launch_bounds__(256)
void k_mlp2(const float* __restrict__ z2,
            const float* __restrict__ W2a, const float* __restrict__ b2a,
            const float* __restrict__ W2b, const float* __restrict__ b2b,
            const float* __restrict__ Wh,  const float* __restrict__ bh,
            float* __restrict__ out) {
    __shared__ float W2a_sm[D * H2];
    __shared__ float W2b_sm[H2 * H2];
    __shared__ float Wh_sm[H2 * OUTD];
    __shared__ float a_sm[ROWS2 * H2];
    __shared__ float b_sm[ROWS2 * H2];
    const int tid = threadIdx.x;
    for (int i = tid; i < D * H2;    i += 256) W2a_sm[i] = W2a[i];
    for (int i = tid; i < H2 * H2;   i += 256) W2b_sm[i] = W2b[i];
    for (int i = tid; i < H2 * OUTD; i += 256) Wh_sm[i]  = Wh[i];
    __syncthreads();

    const int g = tid / H2;
    const int j = tid - g * H2;
    const int row0 = blockIdx.x * ROWS2;
    const int RPG = ROWS2 / 8;
    float bja = b2a[j], bjb = b2b[j];

    for (int rr = 0; rr < RPG; rr++) {
        int r = g * RPG + rr;
        int row = row0 + r;
        if (row < N_NODES) {
            float acc = bja;
            const float* zr = z2 + (long long)row * D;
            #pragma unroll 16
            for (int k = 0; k < D; k++) acc = fmaf(__ldg(zr + k), W2a_sm[k * H2 + j], acc);
            a_sm[r * H2 + j] = fmaxf(acc, 0.0f);
        }
    }
    __syncthreads();
    for (int rr = 0; rr < RPG; rr++) {
        int r = g * RPG + rr;
        int row = row0 + r;
        if (row < N_NODES) {
            float acc = bjb;
            #pragma unroll
            for (int k = 0; k < H2; k++) acc = fmaf(a_sm[r * H2 + k], W2b_sm[k * H2 + j], acc);
            b_sm[r * H2 + j] = fmaxf(acc, 0.0f);
        }
    }
    __syncthreads();
    {
        int r = tid / OUTD;
        int o = tid - r * OUTD;
        int row = row0 + r;
        if (row < N_NODES) {
            float acc = bh[o];
            #pragma unroll
            for (int k = 0; k < H2; k++) acc = fmaf(b_sm[r * H2 + k], Wh_sm[k * OUTD + o], acc);
            out[(long long)row * OUTD + o] = acc;
        }
    }
}

extern "C" void kernel_launch(void* const* d_in, const int* in_sizes, int n_in,
                              void* d_out, int out_size) {
    const float* x    = (const float*)d_in[0];
    const int*   ei   = (const int*)  d_in[1];
    const float* eps1 = (const float*)d_in[2];
    const float* eps2 = (const float*)d_in[3];
    const float* W1a  = (const float*)d_in[4];
    const float* b1a  = (const float*)d_in[5];
    const float* W1b  = (const float*)d_in[6];
    const float* b1b  = (const float*)d_in[7];
    const float* W2a  = (const float*)d_in[8];
    const float* b2a  = (const float*)d_in[9];
    const float* W2b  = (const float*)d_in[10];
    const float* b2b  = (const float*)d_in[11];
    const float* Wh   = (const float*)d_in[12];
    const float* bh   = (const float*)d_in[13];
    float* out = (float*)d_out;

    float *z1, *h1, *z2;
    int *deg, *rowptr, *cursor, *bsum, *ebuf;
    cudaGetSymbolAddress((void**)&z1, g_z1);
    cudaGetSymbolAddress((void**)&h1, g_h1);
    cudaGetSymbolAddress((void**)&z2, g_z2);
    cudaGetSymbolAddress((void**)&deg, g_deg);
    cudaGetSymbolAddress((void**)&rowptr, g_rowptr);
    cudaGetSymbolAddress((void**)&cursor, g_cursor);
    cudaGetSymbolAddress((void**)&bsum, g_bsum);
    cudaGetSymbolAddress((void**)&ebuf, g_ebuf);

    const int eb = (N_EDGES + 255) / 256;
    const int gagg_blocks = (N_NODES * 32 + 255) / 256;   // warp per node
    const int mlp1_blocks = (N_NODES + ROWS1 - 1) / ROWS1;
    const int mlp2_blocks = (N_NODES + ROWS2 - 1) / ROWS2;

    // CSR build (once, shared by both layers)
    cudaMemsetAsync(deg, 0, N_NODES * sizeof(int));
    k_hist<<<eb, 256>>>(ei, deg);
    k_scan1<<<SCAN_NB, SCAN_B>>>(deg, rowptr, bsum);
    k_scan2<<<1, 64>>>(bsum);
    k_scan3<<<SCAN_NB, SCAN_B>>>(rowptr, bsum, cursor);
    k_fill<<<eb, 256>>>(ei, cursor, ebuf);

    // Layer 1
    k_gagg<<<gagg_blocks, 256>>>(x, eps1, rowptr, ebuf, z1);
    k_mlp1<<<mlp1_blocks, GROUPS1 * D>>>(z1, W1a, b1a, W1b, b1b, h1);

    // Layer 2
    k_gagg<<<gagg_blocks, 256>>>(h1, eps2, rowptr, ebuf, z2);
    k_mlp2<<<mlp2_blocks, 256>>>(z2, W2a, b2a, W2b, b2b, Wh, bh, out);
}

// round 4
// speedup vs baseline: 2.5381x; 2.1796x over previous
#include <cuda_runtime.h>

#define N_NODES 50000
#define N_EDGES 800000
#define D       96
#define H2      32
#define OUTD    4
#define CH      (D/4)        // 24 float4 chunks per row
#define SCAN_B  1024
#define SCAN_NB ((N_NODES + SCAN_B - 1) / SCAN_B)   // 49

// Scratch (no allocations allowed)
__device__ float g_z1[N_NODES * D];
__device__ float g_h1[N_NODES * D];
__device__ float g_z2[N_NODES * D];
__device__ int   g_deg[N_NODES];
__device__ int   g_rowptr[N_NODES + 1];
__device__ int   g_cursor[N_NODES];
__device__ int   g_bsum[SCAN_NB];
__device__ int   g_ebuf[N_EDGES];

// ---------------- CSR build ----------------

__global__ void k_hist(const int* __restrict__ ei, int* __restrict__ deg) {
    int e = blockIdx.x * blockDim.x + threadIdx.x;
    if (e < N_EDGES) atomicAdd(&deg[ei[N_EDGES + e]], 1);
}

__global__ __launch_bounds__(SCAN_B)
void k_scan1(const int* __restrict__ deg, int* __restrict__ rowptr, int* __restrict__ bsum) {
    __shared__ int s[SCAN_B];
    int t = threadIdx.x;
    int i = blockIdx.x * SCAN_B + t;
    int v = (i < N_NODES) ? deg[i] : 0;
    s[t] = v;
    __syncthreads();
    for (int off = 1; off < SCAN_B; off <<= 1) {
        int add = (t >= off) ? s[t - off] : 0;
        __syncthreads();
        s[t] += add;
        __syncthreads();
    }
    if (i < N_NODES) rowptr[i] = s[t] - v;
    if (t == SCAN_B - 1) bsum[blockIdx.x] = s[t];
}

__global__ void k_scan2(int* __restrict__ bsum) {
    __shared__ int s[64];
    int t = threadIdx.x;
    int v = (t < SCAN_NB) ? bsum[t] : 0;
    s[t] = v;
    __syncthreads();
    for (int off = 1; off < 64; off <<= 1) {
        int add = (t >= off) ? s[t - off] : 0;
        __syncthreads();
        s[t] += add;
        __syncthreads();
    }
    if (t < SCAN_NB) bsum[t] = s[t] - v;
}

__global__ __launch_bounds__(SCAN_B)
void k_scan3(int* __restrict__ rowptr, const int* __restrict__ bsum, int* __restrict__ cursor) {
    int i = blockIdx.x * SCAN_B + threadIdx.x;
    if (i < N_NODES) {
        int r = rowptr[i] + bsum[blockIdx.x];
        rowptr[i] = r;
        cursor[i] = r;
    }
    if (i == 0) rowptr[N_NODES] = N_EDGES;
}

__global__ void k_fill(const int* __restrict__ ei, int* __restrict__ cursor,
                       int* __restrict__ ebuf) {
    int e = blockIdx.x * blockDim.x + threadIdx.x;
    if (e < N_EDGES) {
        int dst = ei[N_EDGES + e];
        int pos = atomicAdd(&cursor[dst], 1);
        ebuf[pos] = ei[e];
    }
}

// ---------------- fused scale + gather-aggregate ----------------
__global__ __launch_bounds__(256)
void k_gagg(const float* __restrict__ feat, const float* __restrict__ eps,
            const int* __restrict__ rowptr, const int* __restrict__ ebuf,
            float* __restrict__ z) {
    int warp = (blockIdx.x * blockDim.x + threadIdx.x) >> 5;
    int lane = threadIdx.x & 31;
    if (warp >= N_NODES) return;
    int beg = rowptr[warp];
    int end = rowptr[warp + 1];
    const float4* f4 = reinterpret_cast<const float4*>(feat);
    float4 acc = make_float4(0.f, 0.f, 0.f, 0.f);
    if (lane < CH) {
        float s = 1.0f + *eps;
        float4 v = f4[warp * CH + lane];
        acc.x = s * v.x; acc.y = s * v.y; acc.z = s * v.z; acc.w = s * v.w;
    }
    int e = beg;
    for (; e + 4 <= end; e += 4) {
        int s0 = __ldg(&ebuf[e + 0]);
        int s1 = __ldg(&ebuf[e + 1]);
        int s2 = __ldg(&ebuf[e + 2]);
        int s3 = __ldg(&ebuf[e + 3]);
        if (lane < CH) {
            float4 v0 = f4[s0 * CH + lane];
            float4 v1 = f4[s1 * CH + lane];
            float4 v2 = f4[s2 * CH + lane];
            float4 v3 = f4[s3 * CH + lane];
            acc.x += v0.x + v1.x + v2.x + v3.x;
            acc.y += v0.y + v1.y + v2.y + v3.y;
            acc.z += v0.z + v1.z + v2.z + v3.z;
            acc.w += v0.w + v1.w + v2.w + v3.w;
        }
    }
    for (; e < end; e++) {
        int src = __ldg(&ebuf[e]);
        if (lane < CH) {
            float4 v = f4[src * CH + lane];
            acc.x += v.x; acc.y += v.y; acc.z += v.z; acc.w += v.w;
        }
    }
    if (lane < CH) reinterpret_cast<float4*>(z)[warp * CH + lane] = acc;
}

// ---------------- MLP1: register-tiled ----------------
// 64-row tile, 192 threads: thread tile = 8 rows x 4 cols.
// zs row-major with stride 97 (bank spread); W staged in two 48-row halves.
#define M1   64
__global__ __launch_bounds__(192)
void k_mlp1(const float* __restrict__ z,
            const float* __restrict__ W1a, const float* __restrict__ b1a,
            const float* __restrict__ W1b, const float* __restrict__ b1b,
            float* __restrict__ h) {
    __shared__ float zs[M1 * 97];      // 24832 B ; later reused for t
    __shared__ float Wm[48 * 96];      // 18432 B ; one K-half of W
    const int tid = threadIdx.x;
    const int cg = tid % 24;           // column group
    const int rg = tid / 24;           // 0..7
    const int c0 = cg * 4;
    const int r0 = rg * 8;
    const int row0 = blockIdx.x * M1;

    // stage z tile (transposeless, row-major)
    for (int i = tid; i < M1 * CH; i += 192) {
        int r = i / CH, kc = i % CH;
        float4 v = (row0 + r < N_NODES)
                 ? reinterpret_cast<const float4*>(z)[(row0 + r) * CH + kc]
                 : make_float4(0.f, 0.f, 0.f, 0.f);
        zs[r * 97 + kc * 4 + 0] = v.x;
        zs[r * 97 + kc * 4 + 1] = v.y;
        zs[r * 97 + kc * 4 + 2] = v.z;
        zs[r * 97 + kc * 4 + 3] = v.w;
    }

    float4 bias = *reinterpret_cast<const float4*>(&b1a[c0]);
    float acc[8][4];
    #pragma unroll
    for (int i = 0; i < 8; i++) {
        acc[i][0] = bias.x; acc[i][1] = bias.y; acc[i][2] = bias.z; acc[i][3] = bias.w;
    }

    // ---- matmul1: t = relu(z @ W1a + b1a) ----
    for (int kh = 0; kh < 2; kh++) {
        __syncthreads();
        for (int i = tid; i < 48 * 96 / 4; i += 192)
            reinterpret_cast<float4*>(Wm)[i] =
                reinterpret_cast<const float4*>(W1a + kh * 48 * 96)[i];
        __syncthreads();
        #pragma unroll 4
        for (int k = 0; k < 48; k++) {
            int kg = kh * 48 + k;
            float4 w = *reinterpret_cast<float4*>(&Wm[k * 96 + c0]);
            #pragma unroll
            for (int i = 0; i < 8; i++) {
                float zv = zs[(r0 + i) * 97 + kg];
                acc[i][0] = fmaf(zv, w.x, acc[i][0]);
                acc[i][1] = fmaf(zv, w.y, acc[i][1]);
                acc[i][2] = fmaf(zv, w.z, acc[i][2]);
                acc[i][3] = fmaf(zv, w.w, acc[i][3]);
            }
        }
    }
    __syncthreads();   // all zs reads done -> safe to overwrite with t
    #pragma unroll
    for (int i = 0; i < 8; i++) {
        zs[(r0 + i) * 97 + c0 + 0] = fmaxf(acc[i][0], 0.f);
        zs[(r0 + i) * 97 + c0 + 1] = fmaxf(acc[i][1], 0.f);
        zs[(r0 + i) * 97 + c0 + 2] = fmaxf(acc[i][2], 0.f);
        zs[(r0 + i) * 97 + c0 + 3] = fmaxf(acc[i][3], 0.f);
    }

    // ---- matmul2: h = relu(t @ W1b + b1b) ----
    bias = *reinterpret_cast<const float4*>(&b1b[c0]);
    #pragma unroll
    for (int i = 0; i < 8; i++) {
        acc[i][0] = bias.x; acc[i][1] = bias.y; acc[i][2] = bias.z; acc[i][3] = bias.w;
    }
    for (int kh = 0; kh < 2; kh++) {
        __syncthreads();
        for (int i = tid; i < 48 * 96 / 4; i += 192)
            reinterpret_cast<float4*>(Wm)[i] =
                reinterpret_cast<const float4*>(W1b + kh * 48 * 96)[i];
        __syncthreads();
        #pragma unroll 4
        for (int k = 0; k < 48; k++) {
            int kg = kh * 48 + k;
            float4 w = *reinterpret_cast<float4*>(&Wm[k * 96 + c0]);
            #pragma unroll
            for (int i = 0; i < 8; i++) {
                float tv = zs[(r0 + i) * 97 + kg];
                acc[i][0] = fmaf(tv, w.x, acc[i][0]);
                acc[i][1] = fmaf(tv, w.y, acc[i][1]);
                acc[i][2] = fmaf(tv, w.z, acc[i][2]);
                acc[i][3] = fmaf(tv, w.w, acc[i][3]);
            }
        }
    }
    #pragma unroll
    for (int i = 0; i < 8; i++) {
        int row = row0 + r0 + i;
        if (row < N_NODES) {
            float4 o;
            o.x = fmaxf(acc[i][0], 0.f);
            o.y = fmaxf(acc[i][1], 0.f);
            o.z = fmaxf(acc[i][2], 0.f);
            o.w = fmaxf(acc[i][3], 0.f);
            *reinterpret_cast<float4*>(&h[(long long)row * D + c0]) = o;
        }
    }
}

// ---------------- MLP2 + head: register-tiled ----------------
// 64-row tile, 128 threads: thread tile = 4 rows x 4 cols.
#define M2 64
__global__ __launch_bounds__(128)
void k_mlp2(const float* __restrict__ z2,
            const float* __restrict__ W2a, const float* __restrict__ b2a,
            const float* __restrict__ W2b, const float* __restrict__ b2b,
            const float* __restrict__ Wh,  const float* __restrict__ bh,
            float* __restrict__ out) {
    __shared__ float zs[M2 * 97];      // 24832 B ; reused for t (off 0) and b (off 2112)
    __shared__ float W2a_s[D * H2];    // 12288 B
    __shared__ float W2b_s[H2 * H2];   // 4096 B
    __shared__ float Wh_s[H2 * OUTD];  // 512 B
    float* t_s = zs;                   // [64][33]
    float* b_s = zs + M2 * 33;         // [64][33]

    const int tid = threadIdx.x;
    const int cg = tid % 8;            // 8 column groups of 4
    const int rg = tid / 8;            // 0..15
    const int c0 = cg * 4;
    const int r0 = rg * 4;
    const int row0 = blockIdx.x * M2;

    for (int i = tid; i < D * H2 / 4;    i += 128)
        reinterpret_cast<float4*>(W2a_s)[i] = reinterpret_cast<const float4*>(W2a)[i];
    for (int i = tid; i < H2 * H2 / 4;   i += 128)
        reinterpret_cast<float4*>(W2b_s)[i] = reinterpret_cast<const float4*>(W2b)[i];
    for (int i = tid; i < H2 * OUTD; i += 128) Wh_s[i] = Wh[i];
    for (int i = tid; i < M2 * CH; i += 128) {
        int r = i / CH, kc = i % CH;
        float4 v = (row0 + r < N_NODES)
                 ? reinterpret_cast<const float4*>(z2)[(row0 + r) * CH + kc]
                 : make_float4(0.f, 0.f, 0.f, 0.f);
        zs[r * 97 + kc * 4 + 0] = v.x;
        zs[r * 97 + kc * 4 + 1] = v.y;
        zs[r * 97 + kc * 4 + 2] = v.z;
        zs[r * 97 + kc * 4 + 3] = v.w;
    }
    __syncthreads();

    // ---- a = relu(z2 @ W2a + b2a)  [64 x 32] ----
    float4 bias = *reinterpret_cast<const float4*>(&b2a[c0]);
    float acc[4][4];
    #pragma unroll
    for (int i = 0; i < 4; i++) {
        acc[i][0] = bias.x; acc[i][1] = bias.y; acc[i][2] = bias.z; acc[i][3] = bias.w;
    }
    #pragma unroll 4
    for (int k = 0; k < D; k++) {
        float4 w = *reinterpret_cast<float4*>(&W2a_s[k * H2 + c0]);
        #pragma unroll
        for (int i = 0; i < 4; i++) {
            float zv = zs[(r0 + i) * 97 + k];
            acc[i][0] = fmaf(zv, w.x, acc[i][0]);
            acc[i][1] = fmaf(zv, w.y, acc[i][1]);
            acc[i][2] = fmaf(zv, w.z, acc[i][2]);
            acc[i][3] = fmaf(zv, w.w, acc[i][3]);
        }
    }
    __syncthreads();
    #pragma unroll
    for (int i = 0; i < 4; i++) {
        t_s[(r0 + i) * 33 + c0 + 0] = fmaxf(acc[i][0], 0.f);
        t_s[(r0 + i) * 33 + c0 + 1] = fmaxf(acc[i][1], 0.f);
        t_s[(r0 + i) * 33 + c0 + 2] = fmaxf(acc[i][2], 0.f);
        t_s[(r0 + i) * 33 + c0 + 3] = fmaxf(acc[i][3], 0.f);
    }
    __syncthreads();

    // ---- b = relu(a @ W2b + b2b)  [64 x 32] ----
    bias = *reinterpret_cast<const float4*>(&b2b[c0]);
    #pragma unroll
    for (int i = 0; i < 4; i++) {
        acc[i][0] = bias.x; acc[i][1] = bias.y; acc[i][2] = bias.z; acc[i][3] = bias.w;
    }
    #pragma unroll 4
    for (int k = 0; k < H2; k++) {
        float4 w = *reinterpret_cast<float4*>(&W2b_s[k * H2 + c0]);
        #pragma unroll
        for (int i = 0; i < 4; i++) {
            float tv = t_s[(r0 + i) * 33 + k];
            acc[i][0] = fmaf(tv, w.x, acc[i][0]);
            acc[i][1] = fmaf(tv, w.y, acc[i][1]);
            acc[i][2] = fmaf(tv, w.z, acc[i][2]);
            acc[i][3] = fmaf(tv, w.w, acc[i][3]);
        }
    }
    __syncthreads();
    #pragma unroll
    for (int i = 0; i < 4; i++) {
        b_s[(r0 + i) * 33 + c0 + 0] = fmaxf(acc[i][0], 0.f);
        b_s[(r0 + i) * 33 + c0 + 1] = fmaxf(acc[i][1], 0.f);
        b_s[(r0 + i) * 33 + c0 + 2] = fmaxf(acc[i][2], 0.f);
        b_s[(r0 + i) * 33 + c0 + 3] = fmaxf(acc[i][3], 0.f);
    }
    __syncthreads();

    // ---- head: out = b @ Wh + bh  [64 x 4] ----
    if (tid < M2) {
        int row = row0 + tid;
        if (row < N_NODES) {
            float o0 = bh[0], o1 = bh[1], o2 = bh[2], o3 = bh[3];
            #pragma unroll
            for (int k = 0; k < H2; k++) {
                float bv = b_s[tid * 33 + k];
                o0 = fmaf(bv, Wh_s[k * OUTD + 0], o0);
                o1 = fmaf(bv, Wh_s[k * OUTD + 1], o1);
                o2 = fmaf(bv, Wh_s[k * OUTD + 2], o2);
                o3 = fmaf(bv, Wh_s[k * OUTD + 3], o3);
            }
            float4 o = make_float4(o0, o1, o2, o3);
            *reinterpret_cast<float4*>(&out[(long long)row * OUTD]) = o;
        }
    }
}

extern "C" void kernel_launch(void* const* d_in, const int* in_sizes, int n_in,
                              void* d_out, int out_size) {
    const float* x    = (const float*)d_in[0];
    const int*   ei   = (const int*)  d_in[1];
    const float* eps1 = (const float*)d_in[2];
    const float* eps2 = (const float*)d_in[3];
    const float* W1a  = (const float*)d_in[4];
    const float* b1a  = (const float*)d_in[5];
    const float* W1b  = (const float*)d_in[6];
    const float* b1b  = (const float*)d_in[7];
    const float* W2a  = (const float*)d_in[8];
    const float* b2a  = (const float*)d_in[9];
    const float* W2b  = (const float*)d_in[10];
    const float* b2b  = (const float*)d_in[11];
    const float* Wh   = (const float*)d_in[12];
    const float* bh   = (const float*)d_in[13];
    float* out = (float*)d_out;

    float *z1, *h1, *z2;
    int *deg, *rowptr, *cursor, *bsum, *ebuf;
    cudaGetSymbolAddress((void**)&z1, g_z1);
    cudaGetSymbolAddress((void**)&h1, g_h1);
    cudaGetSymbolAddress((void**)&z2, g_z2);
    cudaGetSymbolAddress((void**)&deg, g_deg);
    cudaGetSymbolAddress((void**)&rowptr, g_rowptr);
    cudaGetSymbolAddress((void**)&cursor, g_cursor);
    cudaGetSymbolAddress((void**)&bsum, g_bsum);
    cudaGetSymbolAddress((void**)&ebuf, g_ebuf);

    const int eb = (N_EDGES + 255) / 256;
    const int gagg_blocks = (N_NODES * 32 + 255) / 256;
    const int mlp1_blocks = (N_NODES + M1 - 1) / M1;
    const int mlp2_blocks = (N_NODES + M2 - 1) / M2;

    // CSR build (once, shared by both layers)
    cudaMemsetAsync(deg, 0, N_NODES * sizeof(int));
    k_hist<<<eb, 256>>>(ei, deg);
    k_scan1<<<SCAN_NB, SCAN_B>>>(deg, rowptr, bsum);
    k_scan2<<<1, 64>>>(bsum);
    k_scan3<<<SCAN_NB, SCAN_B>>>(rowptr, bsum, cursor);
    k_fill<<<eb, 256>>>(ei, cursor, ebuf);

    // Layer 1
    k_gagg<<<gagg_blocks, 256>>>(x, eps1, rowptr, ebuf, z1);
    k_mlp1<<<mlp1_blocks, 192>>>(z1, W1a, b1a, W1b, b1b, h1);

    // Layer 2
    k_gagg<<<gagg_blocks, 256>>>(h1, eps2, rowptr, ebuf, z2);
    k_mlp2<<<mlp2_blocks, 128>>>(z2, W2a, b2a, W2b, b2b, Wh, bh, out);
}